// round 8
// baseline (speedup 1.0000x reference)
#include <cuda_runtime.h>
#include <cuda_bf16.h>
#include <cstdint>

// ---------------- problem constants ----------------
#define CC   54
#define CP   27
#define MM   6
#define TT   20
#define NCAND 120
#define CTPAD 56
#define C1F  1.191042e-8f
#define C2F  1.4387752f

// ---------------- mma tile config ----------------
#define TILE_M 128                 // pixels per block tile (8 warps x 16)
#define NNT    15                  // n-tiles of 8 (120 candidates)
#define BROW   384                 // bytes per row (3 segs x 64 bf16)
#define B_IMG_BYTES (NCAND * BROW) // 46080

// smem layout (byte offsets)
#define SM_A    0                  // 128 x 384B swizzled A tile [h|m|l]   (49152)
#define SM_B    49152              // 120 x 384B swizzled cands  [H|M|L]   (46080)
#define SM_C2   95232              // 120 f32 (pad to 512)
#define SM_S2   95744              // 128 f32
#define SM_MINV 96256              // 128 f32
#define SM_MINK 96768              // 128 i32
#define SM_TC   97280              // 20 f32
#define SM_LM   97360              // 8 f32
#define SM_LIB  97392              // 6*54 f32 -> 1296
#define SM_END  98688
#define DYNSMEM (SM_END + 1024)

// ---------------- device globals ----------------
__device__ __align__(16) unsigned char g_Bimg[B_IMG_BYTES];
__device__ __align__(16) float g_candT[NCAND * CTPAD];
__device__ float  g_c2[NCAND];
__device__ float  g_tc[TT];
__device__ float  g_lm[MM];
__device__ double g_obj;

__device__ __forceinline__ uint32_t smem_u32(const void* p) {
    uint32_t a;
    asm("{ .reg .u64 t; cvta.to.shared.u64 t, %1; cvt.u32.u64 %0, t; }" : "=r"(a) : "l"(p));
    return a;
}
__device__ __forceinline__ void ldsm_x4(uint32_t& r0, uint32_t& r1, uint32_t& r2, uint32_t& r3, uint32_t addr) {
    asm volatile("ldmatrix.sync.aligned.m8n8.x4.shared.b16 {%0,%1,%2,%3}, [%4];"
        : "=r"(r0), "=r"(r1), "=r"(r2), "=r"(r3) : "r"(addr));
}
__device__ __forceinline__ void ldsm_x2(uint32_t& r0, uint32_t& r1, uint32_t addr) {
    asm volatile("ldmatrix.sync.aligned.m8n8.x2.shared.b16 {%0,%1}, [%2];"
        : "=r"(r0), "=r"(r1) : "r"(addr));
}
__device__ __forceinline__ void mma16816(float* d, uint32_t a0, uint32_t a1, uint32_t a2, uint32_t a3,
                                         uint32_t b0, uint32_t b1) {
    asm volatile("mma.sync.aligned.m16n8k16.row.col.f32.bf16.bf16.f32 "
        "{%0,%1,%2,%3}, {%4,%5,%6,%7}, {%8,%9}, {%0,%1,%2,%3};"
        : "+f"(d[0]), "+f"(d[1]), "+f"(d[2]), "+f"(d[3])
        : "r"(a0), "r"(a1), "r"(a2), "r"(a3), "r"(b0), "r"(b1));
}

// 3-way bf16 cascade split: x = h + m + l (+ ~2^-27 x)
__device__ __forceinline__ void split3(float x, __nv_bfloat16& h, __nv_bfloat16& m, __nv_bfloat16& l) {
    h = __float2bfloat16(x);
    float r = x - __bfloat162float(h);
    m = __float2bfloat16(r);
    l = __float2bfloat16(r - __bfloat162float(m));
}

// ---------------------------------------------------------------------------
// Setup: candidate spectra -> 3-term split bf16 swizzled B image + fp32 tables.
// ---------------------------------------------------------------------------
__global__ void hadar_setup(const float* __restrict__ s_sky,
                            const float* __restrict__ s_ground,
                            const float* __restrict__ library,
                            const float* __restrict__ wg) {
    __shared__ float sh_xamb[CC];
    __shared__ float sh_B[TT][CC];
    __shared__ float sh_lib[MM][CC];
    int tid = threadIdx.x;
    if (tid == 0) g_obj = 0.0;
    for (int c = tid; c < CC; c += blockDim.x)
        sh_xamb[c] = 0.5f * s_sky[c] + 0.5f * s_ground[c];
    for (int i = tid; i < MM * CC; i += blockDim.x)
        sh_lib[i / CC][i % CC] = library[i];
    for (int i = tid; i < TT * CC; i += blockDim.x) {
        int t = i / CC, c = i % CC;
        float Tk = 250.0f + (100.0f / 19.0f) * (float)t;
        float nu = wg[c];
        sh_B[t][c] = C1F * nu * nu * nu / expm1f(C2F * nu / Tk);
    }
    if (tid < TT) g_tc[tid] = 250.0f + (100.0f / 19.0f) * (float)tid;
    __syncthreads();
    if (tid < MM) {
        float s = 0.0f;
        for (int c = 0; c < CC; c++) s += sh_lib[tid][c];
        g_lm[tid] = s / (float)CC;
    }
    for (int i = tid; i < NCAND * CC; i += blockDim.x) {
        int k = i / CC, c = i % CC;
        int m = k / TT, t = k % TT;
        float e = sh_lib[m][c];
        g_candT[k * CTPAD + c] = e * sh_B[t][c] + (1.0f - e) * sh_xamb[c];
    }
    for (int k = tid; k < NCAND; k += blockDim.x) {
        int m = k / TT, t = k % TT;
        float s = 0.0f;
        for (int c = 0; c < CC; c++) {
            float e = sh_lib[m][c];
            float v = e * sh_B[t][c] + (1.0f - e) * sh_xamb[c];
            s += v * v;
        }
        g_c2[k] = s;
    }
    // B image: row n (candidate), 3 segments of 64 channels: [H | M | L].
    // Channels 54..63 of each segment are zero. XOR-swizzled 384B rows.
    for (int i = tid; i < NCAND * 192; i += blockDim.x) {
        int n = i / 192, c = i % 192;
        int seg = c >> 6, cc = c & 63;
        float v = 0.0f;
        if (cc < CC) {
            int m = n / TT, t = n % TT;
            float e = sh_lib[m][cc];
            v = e * sh_B[t][cc] + (1.0f - e) * sh_xamb[cc];
        }
        __nv_bfloat16 H, M, L;
        split3(v, H, M, L);
        __nv_bfloat16 w = (seg == 0) ? H : (seg == 1) ? M : L;
        uint32_t raw = (uint32_t)(2 * c);
        uint32_t phys = (uint32_t)n * BROW + (raw ^ (((uint32_t)n & 7u) << 4));
        *(__nv_bfloat16*)(g_Bimg + phys) = w;
    }
}

// ---------------------------------------------------------------------------
// Main: persistent HMMA kernel. 256 threads, 8 warps x 16 pixels = 128/tile.
// 6 segment-pairs x 4 k16-steps realize the 6-product split contraction:
//   hH + hM + mH + mM + hL + lH  (error ~1e-8 relative)
// ---------------------------------------------------------------------------
__global__ __launch_bounds__(256, 2)
void hadar_main_mma(const float* __restrict__ s_obs,
                    const float* __restrict__ library,
                    float* __restrict__ out, int N) {
    extern __shared__ unsigned char dynsmem[];
    uint32_t raw = smem_u32(dynsmem);
    uint32_t padb = (1024u - (raw & 1023u)) & 1023u;
    uint32_t sb = raw + padb;
    unsigned char* sp = dynsmem + padb;

    int tid = threadIdx.x, wid = tid >> 5, lane = tid & 31;

    // one-time smem fill
    {
        const uint4* src = (const uint4*)g_Bimg;
        uint4* dst = (uint4*)(sp + SM_B);
        for (int i = tid; i < B_IMG_BYTES / 16; i += 256) dst[i] = src[i];
        float* c2d = (float*)(sp + SM_C2);
        for (int i = tid; i < NCAND; i += 256) c2d[i] = g_c2[i];
        if (tid < TT) ((float*)(sp + SM_TC))[tid] = g_tc[tid];
        if (tid < MM) ((float*)(sp + SM_LM))[tid] = g_lm[tid];
        float* libd = (float*)(sp + SM_LIB);
        for (int i = tid; i < MM * CC; i += 256) libd[i] = library[i];
    }
    __syncthreads();

    long long NN = N;
    int tiles = (N + TILE_M - 1) / TILE_M;
    double acc = 0.0;

    const uint32_t abase = sb + SM_A + (uint32_t)wid * 16u * BROW;
    // A-frag ldmatrix lane addressing
    const int a_mi = lane >> 3;
    const uint32_t a_row = (uint32_t)(((a_mi & 1) << 3) + (lane & 7));
    const uint32_t a_sw = (a_row & 7u) << 4;
    const uint32_t a_hi16 = (uint32_t)((a_mi >> 1) << 4);
    const uint32_t a_rowoff = abase + a_row * BROW;
    // B-frag x4 lane addressing: mi>>1 selects n-subtile, mi&1 selects k-half
    const uint32_t b4_row = (uint32_t)(((lane >> 4) << 3) + (lane & 7));
    const uint32_t b4_sw = ((uint32_t)(lane & 7)) << 4;
    const uint32_t b4_hi16 = (uint32_t)(((lane >> 3) & 1) << 4);
    const uint32_t b4_base = sb + SM_B + b4_row * BROW;
    // B-frag x2 lane addressing (last n-tile)
    const int l15 = lane & 15;
    const uint32_t b2_sw = ((uint32_t)(l15 & 7)) << 4;
    const uint32_t b2_hi16 = (uint32_t)((l15 >> 3) << 4);
    const uint32_t b2_base = sb + SM_B + (uint32_t)(14 * 8 + (l15 & 7)) * BROW;

    // 6 segment pairs: (A-seg byte offset, B-seg byte offset)
    const uint32_t PAIR_A[6] = { 0u,   0u, 128u, 128u,   0u, 256u };
    const uint32_t PAIR_B[6] = { 0u, 128u,   0u, 128u, 256u,   0u };

    for (int tile = blockIdx.x; tile < tiles; tile += gridDim.x) {
        long long base = (long long)tile * TILE_M;

        // ---- stage A: warp owns rows wid*16..+15; segs [h|m|l] ----
#pragma unroll 4
        for (int rr = 0; rr < 16; rr++) {
            int r = (wid << 4) + rr;
            long long n = base + r;
            float x = 0.0f, y = 0.0f;
            if (n < N && lane < CP) {
                float2 v = *(const float2*)(s_obs + n * CC + 2 * lane);
                x = v.x; y = v.y;
            }
            __nv_bfloat16 hx, mx, lx, hy, my, ly;
            split3(x, hx, mx, lx);
            split3(y, hy, my, ly);
            uint32_t hp = ((uint32_t)__bfloat16_as_ushort(hy) << 16) | __bfloat16_as_ushort(hx);
            uint32_t mp = ((uint32_t)__bfloat16_as_ushort(my) << 16) | __bfloat16_as_ushort(mx);
            uint32_t lp = ((uint32_t)__bfloat16_as_ushort(ly) << 16) | __bfloat16_as_ushort(lx);
            float p2 = fmaf(x, x, y * y);
#pragma unroll
            for (int o = 16; o > 0; o >>= 1) p2 += __shfl_xor_sync(0xffffffffu, p2, o);
            if (lane == 0) ((float*)(sp + SM_S2))[r] = p2;
            uint32_t ro = (uint32_t)r * BROW;
            uint32_t sw = ((uint32_t)r & 7u) << 4;
            uint32_t c4 = 4u * (uint32_t)lane;
            unsigned char* ap = sp + SM_A + ro;
            *(uint32_t*)(ap + ((c4)        ^ sw)) = hp;
            *(uint32_t*)(ap + ((128u + c4) ^ sw)) = mp;
            *(uint32_t*)(ap + ((256u + c4) ^ sw)) = lp;
        }
        __syncwarp();

        // ---- HMMA: D[16 x 120] per warp; 6 pairs x 4 k-steps ----
        float d[NNT * 4];
#pragma unroll
        for (int i = 0; i < NNT * 4; i++) d[i] = 0.0f;

#pragma unroll
        for (int pr = 0; pr < 6; pr++) {
            uint32_t aoff = PAIR_A[pr], boff = PAIR_B[pr];
#pragma unroll
            for (int s = 0; s < 4; s++) {
                uint32_t ka = aoff + (uint32_t)s * 32u;
                uint32_t kb = boff + (uint32_t)s * 32u;
                uint32_t a0, a1, a2, a3;
                ldsm_x4(a0, a1, a2, a3, a_rowoff + ((ka + a_hi16) ^ a_sw));
                uint32_t bk4 = (kb + b4_hi16) ^ b4_sw;
#pragma unroll
                for (int q = 0; q < 7; q++) {
                    uint32_t b0, b1, b2, b3;
                    ldsm_x4(b0, b1, b2, b3, b4_base + (uint32_t)q * (16u * BROW) + bk4);
                    mma16816(d + (2 * q) * 4,     a0, a1, a2, a3, b0, b1);
                    mma16816(d + (2 * q + 1) * 4, a0, a1, a2, a3, b2, b3);
                }
                {
                    uint32_t b0, b1;
                    ldsm_x2(b0, b1, b2_base + ((kb + b2_hi16) ^ b2_sw));
                    mma16816(d + 14 * 4, a0, a1, a2, a3, b0, b1);
                }
            }
        }

        // ---- per-lane argmin (rows lane/4 and lane/4+8) ----
        const float* c2s = (const float*)(sp + SM_C2);
        float mva = 3.402823e38f, mvb = 3.402823e38f;
        int mka = 0, mkb = 0;
#pragma unroll
        for (int nt = 0; nt < NNT; nt++) {
            int k0 = nt * 8 + 2 * (lane & 3);
            float c20 = c2s[k0], c21 = c2s[k0 + 1];
            float va0 = fmaf(-2.0f, d[nt * 4 + 0], c20);
            float va1 = fmaf(-2.0f, d[nt * 4 + 1], c21);
            float vb0 = fmaf(-2.0f, d[nt * 4 + 2], c20);
            float vb1 = fmaf(-2.0f, d[nt * 4 + 3], c21);
            if (va0 < mva) { mva = va0; mka = k0; }
            if (va1 < mva) { mva = va1; mka = k0 + 1; }
            if (vb0 < mvb) { mvb = vb0; mkb = k0; }
            if (vb1 < mvb) { mvb = vb1; mkb = k0 + 1; }
        }
#pragma unroll
        for (int off = 1; off <= 2; off <<= 1) {
            float ov = __shfl_xor_sync(0xffffffffu, mva, off);
            int   ok = __shfl_xor_sync(0xffffffffu, mka, off);
            if (ov < mva || (ov == mva && ok < mka)) { mva = ov; mka = ok; }
            ov = __shfl_xor_sync(0xffffffffu, mvb, off);
            ok = __shfl_xor_sync(0xffffffffu, mkb, off);
            if (ov < mvb || (ov == mvb && ok < mkb)) { mvb = ov; mkb = ok; }
        }
        if ((lane & 3) == 0) {
            int ra = (wid << 4) + (lane >> 2);
            ((int*)(sp + SM_MINK))[ra] = mka;
            ((float*)(sp + SM_MINV))[ra] = mva;
            ((int*)(sp + SM_MINK))[ra + 8] = mkb;
            ((float*)(sp + SM_MINV))[ra + 8] = mvb;
        }
        __syncthreads();

        // ---- scalar outputs + loss accumulation ----
        if (tid < TILE_M) {
            long long n = base + tid;
            if (n < N) {
                int kmin = ((const int*)(sp + SM_MINK))[tid];
                int m = kmin / TT;
                out[n] = ((const float*)(sp + SM_TC))[kmin - m * TT];
                out[55 * NN + n] = 0.5f;
                out[56 * NN + n] = 0.0f;
                out[57 * NN + n] = ((const float*)(sp + SM_LM))[m];
                acc += (double)(((const float*)(sp + SM_S2))[tid] +
                                ((const float*)(sp + SM_MINV))[tid]);
            }
        }

        // ---- coalesced best_e + s_recon ----
        {
            int npx = (int)((N - base) < TILE_M ? (N - base) : TILE_M);
            int limit = npx * CP;
            float2* eo = (float2*)(out + NN) + base * CP;
            float2* ro = (float2*)(out + 58 * NN) + base * CP;
            const float* libs = (const float*)(sp + SM_LIB);
            const int* mk = (const int*)(sp + SM_MINK);
            for (int i = tid; i < limit; i += 256) {
                int p = i / CP;
                int j = i - p * CP;
                int k = mk[p];
                int m = k / TT;
                float2 e = *(const float2*)(libs + m * CC + 2 * j);
                float2 rv = __ldg((const float2*)(g_candT + k * CTPAD + 2 * j));
                eo[i] = e;
                ro[i] = rv;
            }
        }
        __syncthreads();
    }

    // ---- objective reduce (reuse A region, loop finished) ----
    double* red = (double*)(sp + SM_A);
    red[tid] = acc;
    __syncthreads();
#pragma unroll
    for (int s = 128; s > 0; s >>= 1) {
        if (tid < s) red[tid] += red[tid + s];
        __syncthreads();
    }
    if (tid == 0) atomicAdd(&g_obj, red[0]);
}

__global__ void hadar_finalize(float* __restrict__ out, int N) {
    out[112LL * N] = (float)(g_obj / (double)N);
}

// ---------------------------------------------------------------------------
extern "C" void kernel_launch(void* const* d_in, const int* in_sizes, int n_in,
                              void* d_out, int out_size) {
    const float* s_obs    = (const float*)d_in[0];
    const float* s_sky    = (const float*)d_in[1];
    const float* s_ground = (const float*)d_in[2];
    const float* library  = (const float*)d_in[3];
    const float* wg       = (const float*)d_in[4];
    float* out = (float*)d_out;
    int C = in_sizes[1];           // 54
    int N = in_sizes[0] / C;       // 1048576

    cudaFuncSetAttribute(hadar_main_mma, cudaFuncAttributeMaxDynamicSharedMemorySize, DYNSMEM);

    hadar_setup<<<1, 512>>>(s_sky, s_ground, library, wg);
    hadar_main_mma<<<296, 256, DYNSMEM>>>(s_obs, library, out, N);
    hadar_finalize<<<1, 1>>>(out, N);
}

// round 10
// speedup vs baseline: 1.5235x; 1.5235x over previous
#include <cuda_runtime.h>
#include <cuda_fp16.h>
#include <cstdint>

// ---------------- problem constants ----------------
#define CC   54
#define CP   27
#define MM   6
#define TT   20
#define NCAND 120
#define CTPAD 56
#define C1F  1.191042e-8f
#define C2F  1.4387752f

// ---------------- mma tile config ----------------
#define TILE_M 128                 // pixels per block tile (8 warps x 16)
#define NNT    15                  // n-tiles of 8 (120 candidates)
#define AROW   128                 // bytes per A row (64 fp16)
#define BROW   128                 // bytes per B row (64 fp16)
#define B_IMG_BYTES (NCAND * BROW) // 15360

// smem layout (byte offsets from 1024-aligned base)
#define SM_A    0                  // 128 x 128B swizzled fp16 A tile      (16384)
#define SM_B    16384              // 120 x 128B swizzled fp16 candidates  (15360)
#define SM_A32  31744              // 128 x 56 f32 exact s_obs rows        (28672)
#define SM_CT   60416              // 120 x 56 f32 exact candidate rows    (26880)
#define SM_C2   87296              // 120 f32 (pad 512)
#define SM_S2   87808              // 128 f32
#define SM_MINV 88320              // 128 f32
#define SM_MINK 88832              // 128 i32
#define SM_TC   89344              // 20 f32
#define SM_LM   89424              // 8 f32
#define SM_LIB  89456              // 6*54 f32
#define SM_END  90752
#define DYNSMEM (SM_END + 1024)

// ---------------- device globals ----------------
__device__ __align__(16) unsigned char g_Bimg[B_IMG_BYTES];
__device__ __align__(16) float g_candT[NCAND * CTPAD];
__device__ float  g_c2[NCAND];
__device__ float  g_tc[TT];
__device__ float  g_lm[MM];
__device__ double g_obj;

__device__ __forceinline__ uint32_t smem_u32(const void* p) {
    uint32_t a;
    asm("{ .reg .u64 t; cvta.to.shared.u64 t, %1; cvt.u32.u64 %0, t; }" : "=r"(a) : "l"(p));
    return a;
}
__device__ __forceinline__ void ldsm_x4(uint32_t& r0, uint32_t& r1, uint32_t& r2, uint32_t& r3, uint32_t addr) {
    asm volatile("ldmatrix.sync.aligned.m8n8.x4.shared.b16 {%0,%1,%2,%3}, [%4];"
        : "=r"(r0), "=r"(r1), "=r"(r2), "=r"(r3) : "r"(addr));
}
__device__ __forceinline__ void ldsm_x2(uint32_t& r0, uint32_t& r1, uint32_t addr) {
    asm volatile("ldmatrix.sync.aligned.m8n8.x2.shared.b16 {%0,%1}, [%2];"
        : "=r"(r0), "=r"(r1) : "r"(addr));
}
__device__ __forceinline__ void mma16816h(float* d, uint32_t a0, uint32_t a1, uint32_t a2, uint32_t a3,
                                          uint32_t b0, uint32_t b1) {
    asm volatile("mma.sync.aligned.m16n8k16.row.col.f32.f16.f16.f32 "
        "{%0,%1,%2,%3}, {%4,%5,%6,%7}, {%8,%9}, {%0,%1,%2,%3};"
        : "+f"(d[0]), "+f"(d[1]), "+f"(d[2]), "+f"(d[3])
        : "r"(a0), "r"(a1), "r"(a2), "r"(a3), "r"(b0), "r"(b1));
}

// ---------------------------------------------------------------------------
// Setup: fp16 swizzled candidate B image + exact fp32 tables.
// ---------------------------------------------------------------------------
__global__ void hadar_setup(const float* __restrict__ s_sky,
                            const float* __restrict__ s_ground,
                            const float* __restrict__ library,
                            const float* __restrict__ wg) {
    __shared__ float sh_xamb[CC];
    __shared__ float sh_B[TT][CC];
    __shared__ float sh_lib[MM][CC];
    int tid = threadIdx.x;
    if (tid == 0) g_obj = 0.0;
    for (int c = tid; c < CC; c += blockDim.x)
        sh_xamb[c] = 0.5f * s_sky[c] + 0.5f * s_ground[c];
    for (int i = tid; i < MM * CC; i += blockDim.x)
        sh_lib[i / CC][i % CC] = library[i];
    for (int i = tid; i < TT * CC; i += blockDim.x) {
        int t = i / CC, c = i % CC;
        float Tk = 250.0f + (100.0f / 19.0f) * (float)t;
        float nu = wg[c];
        sh_B[t][c] = C1F * nu * nu * nu / expm1f(C2F * nu / Tk);
    }
    if (tid < TT) g_tc[tid] = 250.0f + (100.0f / 19.0f) * (float)tid;
    __syncthreads();
    if (tid < MM) {
        float s = 0.0f;
        for (int c = 0; c < CC; c++) s += sh_lib[tid][c];
        g_lm[tid] = s / (float)CC;
    }
    for (int i = tid; i < NCAND * CC; i += blockDim.x) {
        int k = i / CC, c = i % CC;
        int m = k / TT, t = k % TT;
        float e = sh_lib[m][c];
        g_candT[k * CTPAD + c] = e * sh_B[t][c] + (1.0f - e) * sh_xamb[c];
    }
    for (int k = tid; k < NCAND; k += blockDim.x) {
        int m = k / TT, t = k % TT;
        float s = 0.0f;
        for (int c = 0; c < CC; c++) {
            float e = sh_lib[m][c];
            float v = e * sh_B[t][c] + (1.0f - e) * sh_xamb[c];
            s += v * v;
        }
        g_c2[k] = s;
    }
    // fp16 B image: row n (candidate), 64 cols (54 real + 10 zeros), XOR-swizzled.
    for (int i = tid; i < NCAND * 64; i += blockDim.x) {
        int n = i / 64, c = i % 64;
        float v = 0.0f;
        if (c < CC) {
            int m = n / TT, t = n % TT;
            float e = sh_lib[m][c];
            v = e * sh_B[t][c] + (1.0f - e) * sh_xamb[c];
        }
        __half h = __float2half(v);
        uint32_t raw = (uint32_t)(2 * c);
        uint32_t phys = (uint32_t)n * BROW + (raw ^ (((uint32_t)n & 7u) << 4));
        *(__half*)(g_Bimg + phys) = h;
    }
}

// ---------------------------------------------------------------------------
// Main: persistent coarse-fp16-HMMA + sound exact-fp32 refine.
// 256 threads, 8 warps x 16 pixels = 128 px/tile.
// ---------------------------------------------------------------------------
__global__ __launch_bounds__(256, 2)
void hadar_main_mma(const float* __restrict__ s_obs,
                    const float* __restrict__ library,
                    float* __restrict__ out, int N) {
    extern __shared__ unsigned char dynsmem[];
    uint32_t raw = smem_u32(dynsmem);
    uint32_t padb = (1024u - (raw & 1023u)) & 1023u;
    uint32_t sb = raw + padb;
    unsigned char* sp = dynsmem + padb;

    int tid = threadIdx.x, wid = tid >> 5, lane = tid & 31;

    // one-time smem fill
    {
        const uint4* srcB = (const uint4*)g_Bimg;
        uint4* dstB = (uint4*)(sp + SM_B);
        for (int i = tid; i < B_IMG_BYTES / 16; i += 256) dstB[i] = srcB[i];
        const uint4* srcC = (const uint4*)g_candT;
        uint4* dstC = (uint4*)(sp + SM_CT);
        for (int i = tid; i < (NCAND * CTPAD * 4) / 16; i += 256) dstC[i] = srcC[i];
        float* c2d = (float*)(sp + SM_C2);
        for (int i = tid; i < NCAND; i += 256) c2d[i] = g_c2[i];
        if (tid < TT) ((float*)(sp + SM_TC))[tid] = g_tc[tid];
        if (tid < MM) ((float*)(sp + SM_LM))[tid] = g_lm[tid];
        float* libd = (float*)(sp + SM_LIB);
        for (int i = tid; i < MM * CC; i += 256) libd[i] = library[i];
    }
    __syncthreads();

    long long NN = N;
    int tiles = (N + TILE_M - 1) / TILE_M;
    double acc = 0.0;

    const uint32_t abase = sb + SM_A + (uint32_t)wid * 16u * AROW;
    // A-frag ldmatrix lane addressing
    const int a_mi = lane >> 3;
    const uint32_t a_row = (uint32_t)(((a_mi & 1) << 3) + (lane & 7));
    const uint32_t a_sw = (a_row & 7u) << 4;
    const uint32_t a_hi16 = (uint32_t)((a_mi >> 1) << 4);
    const uint32_t a_rowoff = abase + a_row * AROW;
    // B-frag x4 lane addressing
    const uint32_t b4_row = (uint32_t)(((lane >> 4) << 3) + (lane & 7));
    const uint32_t b4_sw = ((uint32_t)(lane & 7)) << 4;
    const uint32_t b4_hi16 = (uint32_t)(((lane >> 3) & 1) << 4);
    const uint32_t b4_base = sb + SM_B + b4_row * BROW;
    // B-frag x2 lane addressing (last n-tile)
    const int l15 = lane & 15;
    const uint32_t b2_sw = ((uint32_t)(l15 & 7)) << 4;
    const uint32_t b2_hi16 = (uint32_t)((l15 >> 3) << 4);
    const uint32_t b2_base = sb + SM_B + (uint32_t)(14 * 8 + (l15 & 7)) * BROW;

    const float* c2s = (const float*)(sp + SM_C2);
    const int ra = (wid << 4) + (lane >> 2);      // row a; row b = ra + 8
    const int colbase = 2 * (lane & 3);

    for (int tile = blockIdx.x; tile < tiles; tile += gridDim.x) {
        long long base = (long long)tile * TILE_M;

        // ---- stage A: warp owns rows wid*16..+15 ----
#pragma unroll 4
        for (int rr = 0; rr < 16; rr++) {
            int r = (wid << 4) + rr;
            long long n = base + r;
            float x = 0.0f, y = 0.0f;
            if (n < N && lane < CP) {
                float2 v = *(const float2*)(s_obs + n * CC + 2 * lane);
                x = v.x; y = v.y;
            }
            __half2 h2 = __floats2half2_rn(x, y);
            uint32_t hp = *(uint32_t*)&h2;
            float p2 = fmaf(x, x, y * y);
#pragma unroll
            for (int o = 16; o > 0; o >>= 1) p2 += __shfl_xor_sync(0xffffffffu, p2, o);
            if (lane == 0) ((float*)(sp + SM_S2))[r] = p2;
            uint32_t sw = ((uint32_t)r & 7u) << 4;
            *(uint32_t*)(sp + SM_A + (uint32_t)r * AROW + ((4u * (uint32_t)lane) ^ sw)) = hp;
            if (lane < 28)
                ((float2*)(sp + SM_A32))[r * 28 + lane] = make_float2(x, y);
        }
        __syncwarp();

        // ---- coarse HMMA: D[16 x 120] per warp, K=64 fp16 ----
        float d[NNT * 4];
#pragma unroll
        for (int i = 0; i < NNT * 4; i++) d[i] = 0.0f;

#pragma unroll
        for (int s = 0; s < 4; s++) {
            uint32_t koff = (uint32_t)s * 32u;
            uint32_t a0, a1, a2, a3;
            ldsm_x4(a0, a1, a2, a3, a_rowoff + ((koff + a_hi16) ^ a_sw));
            uint32_t bk4 = (koff + b4_hi16) ^ b4_sw;
#pragma unroll
            for (int q = 0; q < 7; q++) {
                uint32_t b0, b1, b2, b3;
                ldsm_x4(b0, b1, b2, b3, b4_base + (uint32_t)q * (16u * BROW) + bk4);
                mma16816h(d + (2 * q) * 4,     a0, a1, a2, a3, b0, b1);
                mma16816h(d + (2 * q + 1) * 4, a0, a1, a2, a3, b2, b3);
            }
            {
                uint32_t b0, b1;
                ldsm_x2(b0, b1, b2_base + ((koff + b2_hi16) ^ b2_sw));
                mma16816h(d + 14 * 4, a0, a1, a2, a3, b0, b1);
            }
        }

        // ---- pass 1: per-row m1 = min(val + bound) ----
        float m1a = 3.402823e38f, m1b = 3.402823e38f;
#pragma unroll
        for (int nt = 0; nt < NNT; nt++) {
            int k0 = nt * 8 + colbase;
            float c20 = c2s[k0], c21 = c2s[k0 + 1];
            float dotA0 = d[nt * 4 + 0], dotA1 = d[nt * 4 + 1];
            float dotB0 = d[nt * 4 + 2], dotB1 = d[nt * 4 + 3];
            m1a = fminf(m1a, fmaf(-2.0f, dotA0, c20) + fmaf(0.0022f, dotA0, 1e-6f));
            m1a = fminf(m1a, fmaf(-2.0f, dotA1, c21) + fmaf(0.0022f, dotA1, 1e-6f));
            m1b = fminf(m1b, fmaf(-2.0f, dotB0, c20) + fmaf(0.0022f, dotB0, 1e-6f));
            m1b = fminf(m1b, fmaf(-2.0f, dotB1, c21) + fmaf(0.0022f, dotB1, 1e-6f));
        }
#pragma unroll
        for (int off = 1; off <= 2; off <<= 1) {
            m1a = fminf(m1a, __shfl_xor_sync(0xffffffffu, m1a, off));
            m1b = fminf(m1b, __shfl_xor_sync(0xffffffffu, m1b, off));
        }

        // ---- pass 2: build candidate shortlist masks ----
        uint32_t maskA = 0, maskB = 0;
#pragma unroll
        for (int nt = 0; nt < NNT; nt++) {
            int k0 = nt * 8 + colbase;
            float c20 = c2s[k0], c21 = c2s[k0 + 1];
            float dotA0 = d[nt * 4 + 0], dotA1 = d[nt * 4 + 1];
            float dotB0 = d[nt * 4 + 2], dotB1 = d[nt * 4 + 3];
            if (fmaf(-2.0f, dotA0, c20) - fmaf(0.0022f, dotA0, 1e-6f) <= m1a) maskA |= 1u << (2 * nt);
            if (fmaf(-2.0f, dotA1, c21) - fmaf(0.0022f, dotA1, 1e-6f) <= m1a) maskA |= 1u << (2 * nt + 1);
            if (fmaf(-2.0f, dotB0, c20) - fmaf(0.0022f, dotB0, 1e-6f) <= m1b) maskB |= 1u << (2 * nt);
            if (fmaf(-2.0f, dotB1, c21) - fmaf(0.0022f, dotB1, 1e-6f) <= m1b) maskB |= 1u << (2 * nt + 1);
        }

        // ---- pass 3: exact fp32 refine of shortlisted candidates ----
        float bva = 3.402823e38f, bvb = 3.402823e38f;
        int bka = NCAND, bkb = NCAND;
        {
            const float2* srowA = (const float2*)(sp + SM_A32) + ra * 28;
            uint32_t mk = maskA;
            while (mk) {
                int i = __ffs(mk) - 1; mk &= mk - 1;
                int k = ((i >> 1) << 3) + colbase + (i & 1);
                const float2* crow = (const float2*)(sp + SM_CT + (uint32_t)k * (CTPAD * 4));
                float dt = 0.0f;
#pragma unroll
                for (int j = 0; j < CP; j++) {
                    float2 sv = srowA[j], cv = crow[j];
                    dt = fmaf(sv.x, cv.x, dt);
                    dt = fmaf(sv.y, cv.y, dt);
                }
                float ev = fmaf(-2.0f, dt, c2s[k]);
                if (ev < bva || (ev == bva && k < bka)) { bva = ev; bka = k; }
            }
            const float2* srowB = srowA + 8 * 28;
            mk = maskB;
            while (mk) {
                int i = __ffs(mk) - 1; mk &= mk - 1;
                int k = ((i >> 1) << 3) + colbase + (i & 1);
                const float2* crow = (const float2*)(sp + SM_CT + (uint32_t)k * (CTPAD * 4));
                float dt = 0.0f;
#pragma unroll
                for (int j = 0; j < CP; j++) {
                    float2 sv = srowB[j], cv = crow[j];
                    dt = fmaf(sv.x, cv.x, dt);
                    dt = fmaf(sv.y, cv.y, dt);
                }
                float ev = fmaf(-2.0f, dt, c2s[k]);
                if (ev < bvb || (ev == bvb && k < bkb)) { bvb = ev; bkb = k; }
            }
        }
        // quad lexicographic reduce (first-min tie rule)
#pragma unroll
        for (int off = 1; off <= 2; off <<= 1) {
            float ov = __shfl_xor_sync(0xffffffffu, bva, off);
            int   ok = __shfl_xor_sync(0xffffffffu, bka, off);
            if (ov < bva || (ov == bva && ok < bka)) { bva = ov; bka = ok; }
            ov = __shfl_xor_sync(0xffffffffu, bvb, off);
            ok = __shfl_xor_sync(0xffffffffu, bkb, off);
            if (ov < bvb || (ov == bvb && ok < bkb)) { bvb = ov; bkb = ok; }
        }
        if ((lane & 3) == 0) {
            ((int*)(sp + SM_MINK))[ra] = bka;
            ((float*)(sp + SM_MINV))[ra] = bva;
            ((int*)(sp + SM_MINK))[ra + 8] = bkb;
            ((float*)(sp + SM_MINV))[ra + 8] = bvb;
        }
        __syncthreads();

        // ---- scalar outputs + loss accumulation ----
        if (tid < TILE_M) {
            long long n = base + tid;
            if (n < N) {
                int kmin = ((const int*)(sp + SM_MINK))[tid];
                int m = kmin / TT;
                out[n] = ((const float*)(sp + SM_TC))[kmin - m * TT];
                out[55 * NN + n] = 0.5f;
                out[56 * NN + n] = 0.0f;
                out[57 * NN + n] = ((const float*)(sp + SM_LM))[m];
                acc += (double)(((const float*)(sp + SM_S2))[tid] +
                                ((const float*)(sp + SM_MINV))[tid]);
            }
        }

        // ---- coalesced best_e + s_recon ----
        {
            int npx = (int)((N - base) < TILE_M ? (N - base) : TILE_M);
            int limit = npx * CP;
            float2* eo = (float2*)(out + NN) + base * CP;
            float2* ro = (float2*)(out + 58 * NN) + base * CP;
            const float* libs = (const float*)(sp + SM_LIB);
            const int* mk = (const int*)(sp + SM_MINK);
            for (int i = tid; i < limit; i += 256) {
                int p = i / CP;
                int j = i - p * CP;
                int k = mk[p];
                int m = k / TT;
                float2 e = *(const float2*)(libs + m * CC + 2 * j);
                float2 rv = ((const float2*)(sp + SM_CT + (uint32_t)k * (CTPAD * 4)))[j];
                eo[i] = e;
                ro[i] = rv;
            }
        }
        __syncthreads();
    }

    // ---- objective reduce (reuse A region, loop finished) ----
    double* red = (double*)(sp + SM_A);
    red[tid] = acc;
    __syncthreads();
#pragma unroll
    for (int s = 128; s > 0; s >>= 1) {
        if (tid < s) red[tid] += red[tid + s];
        __syncthreads();
    }
    if (tid == 0) atomicAdd(&g_obj, red[0]);
}

__global__ void hadar_finalize(float* __restrict__ out, int N) {
    out[112LL * N] = (float)(g_obj / (double)N);
}

// ---------------------------------------------------------------------------
extern "C" void kernel_launch(void* const* d_in, const int* in_sizes, int n_in,
                              void* d_out, int out_size) {
    const float* s_obs    = (const float*)d_in[0];
    const float* s_sky    = (const float*)d_in[1];
    const float* s_ground = (const float*)d_in[2];
    const float* library  = (const float*)d_in[3];
    const float* wg       = (const float*)d_in[4];
    float* out = (float*)d_out;
    int C = in_sizes[1];           // 54
    int N = in_sizes[0] / C;       // 1048576

    cudaFuncSetAttribute(hadar_main_mma, cudaFuncAttributeMaxDynamicSharedMemorySize, DYNSMEM);

    hadar_setup<<<1, 512>>>(s_sky, s_ground, library, wg);
    hadar_main_mma<<<296, 256, DYNSMEM>>>(s_obs, library, out, N);
    hadar_finalize<<<1, 1>>>(out, N);
}

// round 11
// speedup vs baseline: 2.1397x; 1.4045x over previous
#include <cuda_runtime.h>
#include <cuda_fp16.h>
#include <cstdint>

// ---------------- problem constants ----------------
#define CC   54
#define CP   27
#define MM   6
#define TT   20
#define NCAND 120
#define CTPAD 56
#define C1F  1.191042e-8f
#define C2F  1.4387752f

// ---------------- mma tile config ----------------
#define TILE_M 128                 // pixels per block tile (8 warps x 16)
#define NNT    15                  // n-tiles of 8 (120 candidates)
#define AROW   128                 // bytes per A row (64 fp16)
#define BROW   128                 // bytes per B row (64 fp16)
#define B_IMG_BYTES (NCAND * BROW) // 15360

// smem layout (byte offsets from 1024-aligned base)
#define SM_A    0                  // 128 x 128B swizzled fp16 A tile      (16384)
#define SM_B    16384              // 120 x 128B swizzled fp16 candidates  (15360)
#define SM_A32  31744              // 128 x 56 f32 exact s_obs rows        (28672)
#define SM_CT   60416              // 120 x 56 f32 exact candidate rows    (26880)
#define SM_C2   87296              // 120 f32 (pad 512)
#define SM_MINV 87808              // 128 f32
#define SM_MINK 88320              // 128 i32
#define SM_TC   88832              // 20 f32
#define SM_LM   88912              // 8 f32
#define SM_LIB  88944              // 6*54 f32
#define SM_END  90240
#define DYNSMEM (SM_END + 1024)

// ---------------- device globals ----------------
__device__ __align__(16) unsigned char g_Bimg[B_IMG_BYTES];
__device__ __align__(16) float g_candT[NCAND * CTPAD];
__device__ float  g_c2[NCAND];
__device__ float  g_tc[TT];
__device__ float  g_lm[MM];
__device__ double g_obj;

__device__ __forceinline__ uint32_t smem_u32(const void* p) {
    uint32_t a;
    asm("{ .reg .u64 t; cvta.to.shared.u64 t, %1; cvt.u32.u64 %0, t; }" : "=r"(a) : "l"(p));
    return a;
}
__device__ __forceinline__ void ldsm_x4(uint32_t& r0, uint32_t& r1, uint32_t& r2, uint32_t& r3, uint32_t addr) {
    asm volatile("ldmatrix.sync.aligned.m8n8.x4.shared.b16 {%0,%1,%2,%3}, [%4];"
        : "=r"(r0), "=r"(r1), "=r"(r2), "=r"(r3) : "r"(addr));
}
__device__ __forceinline__ void ldsm_x2(uint32_t& r0, uint32_t& r1, uint32_t addr) {
    asm volatile("ldmatrix.sync.aligned.m8n8.x2.shared.b16 {%0,%1}, [%2];"
        : "=r"(r0), "=r"(r1) : "r"(addr));
}
__device__ __forceinline__ void mma16816h(float* d, uint32_t a0, uint32_t a1, uint32_t a2, uint32_t a3,
                                          uint32_t b0, uint32_t b1) {
    asm volatile("mma.sync.aligned.m16n8k16.row.col.f32.f16.f16.f32 "
        "{%0,%1,%2,%3}, {%4,%5,%6,%7}, {%8,%9}, {%0,%1,%2,%3};"
        : "+f"(d[0]), "+f"(d[1]), "+f"(d[2]), "+f"(d[3])
        : "r"(a0), "r"(a1), "r"(a2), "r"(a3), "r"(b0), "r"(b1));
}

// ---------------------------------------------------------------------------
// Setup: fp16 swizzled candidate B image + exact fp32 tables.
// ---------------------------------------------------------------------------
__global__ void hadar_setup(const float* __restrict__ s_sky,
                            const float* __restrict__ s_ground,
                            const float* __restrict__ library,
                            const float* __restrict__ wg) {
    __shared__ float sh_xamb[CC];
    __shared__ float sh_B[TT][CC];
    __shared__ float sh_lib[MM][CC];
    int tid = threadIdx.x;
    if (tid == 0) g_obj = 0.0;
    for (int c = tid; c < CC; c += blockDim.x)
        sh_xamb[c] = 0.5f * s_sky[c] + 0.5f * s_ground[c];
    for (int i = tid; i < MM * CC; i += blockDim.x)
        sh_lib[i / CC][i % CC] = library[i];
    for (int i = tid; i < TT * CC; i += blockDim.x) {
        int t = i / CC, c = i % CC;
        float Tk = 250.0f + (100.0f / 19.0f) * (float)t;
        float nu = wg[c];
        sh_B[t][c] = C1F * nu * nu * nu / expm1f(C2F * nu / Tk);
    }
    if (tid < TT) g_tc[tid] = 250.0f + (100.0f / 19.0f) * (float)tid;
    __syncthreads();
    if (tid < MM) {
        float s = 0.0f;
        for (int c = 0; c < CC; c++) s += sh_lib[tid][c];
        g_lm[tid] = s / (float)CC;
    }
    for (int i = tid; i < NCAND * CC; i += blockDim.x) {
        int k = i / CC, c = i % CC;
        int m = k / TT, t = k % TT;
        float e = sh_lib[m][c];
        g_candT[k * CTPAD + c] = e * sh_B[t][c] + (1.0f - e) * sh_xamb[c];
    }
    for (int k = tid; k < NCAND; k += blockDim.x) {
        int m = k / TT, t = k % TT;
        float s = 0.0f;
        for (int c = 0; c < CC; c++) {
            float e = sh_lib[m][c];
            float v = e * sh_B[t][c] + (1.0f - e) * sh_xamb[c];
            s += v * v;
        }
        g_c2[k] = s;
    }
    // fp16 B image: row n (candidate), 64 cols (54 real + 10 zeros), XOR-swizzled.
    for (int i = tid; i < NCAND * 64; i += blockDim.x) {
        int n = i / 64, c = i % 64;
        float v = 0.0f;
        if (c < CC) {
            int m = n / TT, t = n % TT;
            float e = sh_lib[m][c];
            v = e * sh_B[t][c] + (1.0f - e) * sh_xamb[c];
        }
        __half h = __float2half(v);
        uint32_t raw = (uint32_t)(2 * c);
        uint32_t phys = (uint32_t)n * BROW + (raw ^ (((uint32_t)n & 7u) << 4));
        *(__half*)(g_Bimg + phys) = h;
    }
}

// ---------------------------------------------------------------------------
// Main: persistent coarse-fp16-HMMA + sound exact-fp32 refine, pipelined LDG.
// 256 threads, 8 warps x 16 pixels = 128 px/tile.
// ---------------------------------------------------------------------------
__global__ __launch_bounds__(256, 2)
void hadar_main_mma(const float* __restrict__ s_obs,
                    const float* __restrict__ library,
                    float* __restrict__ out, int N) {
    extern __shared__ unsigned char dynsmem[];
    uint32_t raw = smem_u32(dynsmem);
    uint32_t padb = (1024u - (raw & 1023u)) & 1023u;
    uint32_t sb = raw + padb;
    unsigned char* sp = dynsmem + padb;

    int tid = threadIdx.x, wid = tid >> 5, lane = tid & 31;

    // one-time smem fill
    {
        const uint4* srcB = (const uint4*)g_Bimg;
        uint4* dstB = (uint4*)(sp + SM_B);
        for (int i = tid; i < B_IMG_BYTES / 16; i += 256) dstB[i] = srcB[i];
        const uint4* srcC = (const uint4*)g_candT;
        uint4* dstC = (uint4*)(sp + SM_CT);
        for (int i = tid; i < (NCAND * CTPAD * 4) / 16; i += 256) dstC[i] = srcC[i];
        float* c2d = (float*)(sp + SM_C2);
        for (int i = tid; i < NCAND; i += 256) c2d[i] = g_c2[i];
        if (tid < TT) ((float*)(sp + SM_TC))[tid] = g_tc[tid];
        if (tid < MM) ((float*)(sp + SM_LM))[tid] = g_lm[tid];
        float* libd = (float*)(sp + SM_LIB);
        for (int i = tid; i < MM * CC; i += 256) libd[i] = library[i];
    }
    __syncthreads();

    long long NN = N;
    int tiles = (N + TILE_M - 1) / TILE_M;
    double acc = 0.0;            // Σ minv (pixels) + Σ x^2+y^2 (this thread's loads)

    const uint32_t abase = sb + SM_A + (uint32_t)wid * 16u * AROW;
    const int a_mi = lane >> 3;
    const uint32_t a_row = (uint32_t)(((a_mi & 1) << 3) + (lane & 7));
    const uint32_t a_sw = (a_row & 7u) << 4;
    const uint32_t a_hi16 = (uint32_t)((a_mi >> 1) << 4);
    const uint32_t a_rowoff = abase + a_row * AROW;
    const uint32_t b4_row = (uint32_t)(((lane >> 4) << 3) + (lane & 7));
    const uint32_t b4_sw = ((uint32_t)(lane & 7)) << 4;
    const uint32_t b4_hi16 = (uint32_t)(((lane >> 3) & 1) << 4);
    const uint32_t b4_base = sb + SM_B + b4_row * BROW;
    const int l15 = lane & 15;
    const uint32_t b2_sw = ((uint32_t)(l15 & 7)) << 4;
    const uint32_t b2_hi16 = (uint32_t)((l15 >> 3) << 4);
    const uint32_t b2_base = sb + SM_B + (uint32_t)(14 * 8 + (l15 & 7)) * BROW;

    const float* c2s = (const float*)(sp + SM_C2);
    const int ra = (wid << 4) + (lane >> 2);      // row a; row b = ra + 8
    const int colbase = 2 * (lane & 3);

    // ---- prologue: prefetch first tile into registers (MLP=16) ----
    float2 pv[16];
    {
        long long base0 = (long long)blockIdx.x * TILE_M;
#pragma unroll
        for (int rr = 0; rr < 16; rr++) {
            int r = (wid << 4) + rr;
            long long n = base0 + r;
            pv[rr] = make_float2(0.0f, 0.0f);
            if (blockIdx.x < tiles && n < N && lane < CP)
                pv[rr] = *(const float2*)(s_obs + n * CC + 2 * lane);
        }
    }

    for (int tile = blockIdx.x; tile < tiles; tile += gridDim.x) {
        long long base = (long long)tile * TILE_M;

        // ---- stage A from registers: fp16 swizzled + fp32 copy ----
        float tp2 = 0.0f;
#pragma unroll
        for (int rr = 0; rr < 16; rr++) {
            int r = (wid << 4) + rr;
            float x = pv[rr].x, y = pv[rr].y;
            tp2 = fmaf(x, x, fmaf(y, y, tp2));
            __half2 h2 = __floats2half2_rn(x, y);
            uint32_t hp = *(uint32_t*)&h2;
            uint32_t sw = ((uint32_t)r & 7u) << 4;
            *(uint32_t*)(sp + SM_A + (uint32_t)r * AROW + ((4u * (uint32_t)lane) ^ sw)) = hp;
            if (lane < 28)
                ((float2*)(sp + SM_A32))[r * 28 + lane] = make_float2(x, y);
        }
        acc += (double)tp2;
        __syncwarp();

        // ---- coarse HMMA: D[16 x 120] per warp, K=64 fp16 ----
        float d[NNT * 4];
#pragma unroll
        for (int i = 0; i < NNT * 4; i++) d[i] = 0.0f;

#pragma unroll
        for (int s = 0; s < 4; s++) {
            uint32_t koff = (uint32_t)s * 32u;
            uint32_t a0, a1, a2, a3;
            ldsm_x4(a0, a1, a2, a3, a_rowoff + ((koff + a_hi16) ^ a_sw));
            uint32_t bk4 = (koff + b4_hi16) ^ b4_sw;
#pragma unroll
            for (int q = 0; q < 7; q++) {
                uint32_t b0, b1, b2, b3;
                ldsm_x4(b0, b1, b2, b3, b4_base + (uint32_t)q * (16u * BROW) + bk4);
                mma16816h(d + (2 * q) * 4,     a0, a1, a2, a3, b0, b1);
                mma16816h(d + (2 * q + 1) * 4, a0, a1, a2, a3, b2, b3);
            }
            {
                uint32_t b0, b1;
                ldsm_x2(b0, b1, b2_base + ((koff + b2_hi16) ^ b2_sw));
                mma16816h(d + 14 * 4, a0, a1, a2, a3, b0, b1);
            }
        }

        // ---- pass 1: per-row m1 = min(val + bound) ----
        float m1a = 3.402823e38f, m1b = 3.402823e38f;
#pragma unroll
        for (int nt = 0; nt < NNT; nt++) {
            int k0 = nt * 8 + colbase;
            float c20 = c2s[k0], c21 = c2s[k0 + 1];
            float dotA0 = d[nt * 4 + 0], dotA1 = d[nt * 4 + 1];
            float dotB0 = d[nt * 4 + 2], dotB1 = d[nt * 4 + 3];
            m1a = fminf(m1a, fmaf(-2.0f, dotA0, c20) + fmaf(0.0022f, dotA0, 1e-6f));
            m1a = fminf(m1a, fmaf(-2.0f, dotA1, c21) + fmaf(0.0022f, dotA1, 1e-6f));
            m1b = fminf(m1b, fmaf(-2.0f, dotB0, c20) + fmaf(0.0022f, dotB0, 1e-6f));
            m1b = fminf(m1b, fmaf(-2.0f, dotB1, c21) + fmaf(0.0022f, dotB1, 1e-6f));
        }
#pragma unroll
        for (int off = 1; off <= 2; off <<= 1) {
            m1a = fminf(m1a, __shfl_xor_sync(0xffffffffu, m1a, off));
            m1b = fminf(m1b, __shfl_xor_sync(0xffffffffu, m1b, off));
        }

        // ---- pass 2: shortlist masks ----
        uint32_t maskA = 0, maskB = 0;
#pragma unroll
        for (int nt = 0; nt < NNT; nt++) {
            int k0 = nt * 8 + colbase;
            float c20 = c2s[k0], c21 = c2s[k0 + 1];
            float dotA0 = d[nt * 4 + 0], dotA1 = d[nt * 4 + 1];
            float dotB0 = d[nt * 4 + 2], dotB1 = d[nt * 4 + 3];
            if (fmaf(-2.0f, dotA0, c20) - fmaf(0.0022f, dotA0, 1e-6f) <= m1a) maskA |= 1u << (2 * nt);
            if (fmaf(-2.0f, dotA1, c21) - fmaf(0.0022f, dotA1, 1e-6f) <= m1a) maskA |= 1u << (2 * nt + 1);
            if (fmaf(-2.0f, dotB0, c20) - fmaf(0.0022f, dotB0, 1e-6f) <= m1b) maskB |= 1u << (2 * nt);
            if (fmaf(-2.0f, dotB1, c21) - fmaf(0.0022f, dotB1, 1e-6f) <= m1b) maskB |= 1u << (2 * nt + 1);
        }

        // ---- pass 3: exact fp32 refine ----
        float bva = 3.402823e38f, bvb = 3.402823e38f;
        int bka = NCAND, bkb = NCAND;
        {
            const float2* srowA = (const float2*)(sp + SM_A32) + ra * 28;
            uint32_t mk = maskA;
            while (mk) {
                int i = __ffs(mk) - 1; mk &= mk - 1;
                int k = ((i >> 1) << 3) + colbase + (i & 1);
                const float2* crow = (const float2*)(sp + SM_CT + (uint32_t)k * (CTPAD * 4));
                float dt = 0.0f;
#pragma unroll
                for (int j = 0; j < CP; j++) {
                    float2 sv = srowA[j], cv = crow[j];
                    dt = fmaf(sv.x, cv.x, dt);
                    dt = fmaf(sv.y, cv.y, dt);
                }
                float ev = fmaf(-2.0f, dt, c2s[k]);
                if (ev < bva || (ev == bva && k < bka)) { bva = ev; bka = k; }
            }
            const float2* srowB = srowA + 8 * 28;
            mk = maskB;
            while (mk) {
                int i = __ffs(mk) - 1; mk &= mk - 1;
                int k = ((i >> 1) << 3) + colbase + (i & 1);
                const float2* crow = (const float2*)(sp + SM_CT + (uint32_t)k * (CTPAD * 4));
                float dt = 0.0f;
#pragma unroll
                for (int j = 0; j < CP; j++) {
                    float2 sv = srowB[j], cv = crow[j];
                    dt = fmaf(sv.x, cv.x, dt);
                    dt = fmaf(sv.y, cv.y, dt);
                }
                float ev = fmaf(-2.0f, dt, c2s[k]);
                if (ev < bvb || (ev == bvb && k < bkb)) { bvb = ev; bkb = k; }
            }
        }
#pragma unroll
        for (int off = 1; off <= 2; off <<= 1) {
            float ov = __shfl_xor_sync(0xffffffffu, bva, off);
            int   ok = __shfl_xor_sync(0xffffffffu, bka, off);
            if (ov < bva || (ov == bva && ok < bka)) { bva = ov; bka = ok; }
            ov = __shfl_xor_sync(0xffffffffu, bvb, off);
            ok = __shfl_xor_sync(0xffffffffu, bkb, off);
            if (ov < bvb || (ov == bvb && ok < bkb)) { bvb = ov; bkb = ok; }
        }
        if ((lane & 3) == 0) {
            ((int*)(sp + SM_MINK))[ra] = bka;
            ((float*)(sp + SM_MINV))[ra] = bva;
            ((int*)(sp + SM_MINK))[ra + 8] = bkb;
            ((float*)(sp + SM_MINV))[ra + 8] = bvb;
        }
        __syncthreads();

        // ---- prefetch next tile into registers (flies during epilogue) ----
        {
            int ntile = tile + gridDim.x;
            long long nbase = (long long)ntile * TILE_M;
#pragma unroll
            for (int rr = 0; rr < 16; rr++) {
                int r = (wid << 4) + rr;
                long long n = nbase + r;
                pv[rr] = make_float2(0.0f, 0.0f);
                if (ntile < tiles && n < N && lane < CP)
                    pv[rr] = *(const float2*)(s_obs + n * CC + 2 * lane);
            }
        }

        // ---- scalar outputs + loss accumulation ----
        if (tid < TILE_M) {
            long long n = base + tid;
            if (n < N) {
                int kmin = ((const int*)(sp + SM_MINK))[tid];
                int m = kmin / TT;
                out[n] = ((const float*)(sp + SM_TC))[kmin - m * TT];
                out[55 * NN + n] = 0.5f;
                out[56 * NN + n] = 0.0f;
                out[57 * NN + n] = ((const float*)(sp + SM_LM))[m];
                acc += (double)(((const float*)(sp + SM_MINV))[tid]);
            }
        }

        // ---- coalesced best_e + s_recon ----
        {
            int npx = (int)((N - base) < TILE_M ? (N - base) : TILE_M);
            int limit = npx * CP;
            float2* eo = (float2*)(out + NN) + base * CP;
            float2* ro = (float2*)(out + 58 * NN) + base * CP;
            const float* libs = (const float*)(sp + SM_LIB);
            const int* mk = (const int*)(sp + SM_MINK);
            for (int i = tid; i < limit; i += 256) {
                int p = i / CP;
                int j = i - p * CP;
                int k = mk[p];
                int m = k / TT;
                float2 e = *(const float2*)(libs + m * CC + 2 * j);
                float2 rv = ((const float2*)(sp + SM_CT + (uint32_t)k * (CTPAD * 4)))[j];
                eo[i] = e;
                ro[i] = rv;
            }
        }
        __syncthreads();
    }

    // ---- objective reduce (reuse A region, loop finished) ----
    double* red = (double*)(sp + SM_A);
    red[tid] = acc;
    __syncthreads();
#pragma unroll
    for (int s = 128; s > 0; s >>= 1) {
        if (tid < s) red[tid] += red[tid + s];
        __syncthreads();
    }
    if (tid == 0) atomicAdd(&g_obj, red[0]);
}

__global__ void hadar_finalize(float* __restrict__ out, int N) {
    out[112LL * N] = (float)(g_obj / (double)N);
}

// ---------------------------------------------------------------------------
extern "C" void kernel_launch(void* const* d_in, const int* in_sizes, int n_in,
                              void* d_out, int out_size) {
    const float* s_obs    = (const float*)d_in[0];
    const float* s_sky    = (const float*)d_in[1];
    const float* s_ground = (const float*)d_in[2];
    const float* library  = (const float*)d_in[3];
    const float* wg       = (const float*)d_in[4];
    float* out = (float*)d_out;
    int C = in_sizes[1];           // 54
    int N = in_sizes[0] / C;       // 1048576

    cudaFuncSetAttribute(hadar_main_mma, cudaFuncAttributeMaxDynamicSharedMemorySize, DYNSMEM);

    hadar_setup<<<1, 512>>>(s_sky, s_ground, library, wg);
    hadar_main_mma<<<296, 256, DYNSMEM>>>(s_obs, library, out, N);
    hadar_finalize<<<1, 1>>>(out, N);
}

// round 12
// speedup vs baseline: 2.2938x; 1.0720x over previous
#include <cuda_runtime.h>
#include <cuda_fp16.h>
#include <cstdint>

// ---------------- problem constants ----------------
#define CC   54
#define CP   27
#define MM   6
#define TT   20
#define NCAND 120
#define CTPAD 56
#define C1F  1.191042e-8f
#define C2F  1.4387752f

// ---------------- mma tile config ----------------
#define TILE_M 128                 // pixels per block tile (8 warps x 16)
#define NNT    15                  // n-tiles of 8 (120 candidates)
#define AROW   128                 // bytes per A row (64 fp16)
#define BROW   128                 // bytes per B row (64 fp16)
#define B_IMG_BYTES (NCAND * BROW) // 15360

// smem layout (byte offsets from 1024-aligned base)
#define SM_A    0                  // 128 x 128B swizzled fp16 A tile      (16384)
#define SM_B    16384              // 120 x 128B swizzled fp16 candidates  (15360)
#define SM_A32  31744              // 128 x 56 f32 exact s_obs rows        (28672)
#define SM_CT   60416              // 120 x 56 f32 exact candidate rows    (26880)
#define SM_C2   87296              // 120 f32 (pad 512)
#define SM_MINV 87808              // 128 f32
#define SM_MINK 88320              // 128 i32
#define SM_TC   88832              // 20 f32
#define SM_LM   88912              // 8 f32
#define SM_LIB  88944              // 6*54 f32
#define SM_END  90240
#define DYNSMEM (SM_END + 1024)

// ---------------- device globals ----------------
__device__ __align__(16) unsigned char g_Bimg[B_IMG_BYTES];
__device__ __align__(16) float g_candT[NCAND * CTPAD];
__device__ float  g_c2[NCAND];
__device__ float  g_tc[TT];
__device__ float  g_lm[MM];
__device__ double g_obj;

__device__ __forceinline__ uint32_t smem_u32(const void* p) {
    uint32_t a;
    asm("{ .reg .u64 t; cvta.to.shared.u64 t, %1; cvt.u32.u64 %0, t; }" : "=r"(a) : "l"(p));
    return a;
}
__device__ __forceinline__ void ldsm_x4(uint32_t& r0, uint32_t& r1, uint32_t& r2, uint32_t& r3, uint32_t addr) {
    asm volatile("ldmatrix.sync.aligned.m8n8.x4.shared.b16 {%0,%1,%2,%3}, [%4];"
        : "=r"(r0), "=r"(r1), "=r"(r2), "=r"(r3) : "r"(addr));
}
__device__ __forceinline__ void ldsm_x2(uint32_t& r0, uint32_t& r1, uint32_t addr) {
    asm volatile("ldmatrix.sync.aligned.m8n8.x2.shared.b16 {%0,%1}, [%2];"
        : "=r"(r0), "=r"(r1) : "r"(addr));
}
__device__ __forceinline__ void mma16816h(float* d, uint32_t a0, uint32_t a1, uint32_t a2, uint32_t a3,
                                          uint32_t b0, uint32_t b1) {
    asm volatile("mma.sync.aligned.m16n8k16.row.col.f32.f16.f16.f32 "
        "{%0,%1,%2,%3}, {%4,%5,%6,%7}, {%8,%9}, {%0,%1,%2,%3};"
        : "+f"(d[0]), "+f"(d[1]), "+f"(d[2]), "+f"(d[3])
        : "r"(a0), "r"(a1), "r"(a2), "r"(a3), "r"(b0), "r"(b1));
}

// ---------------------------------------------------------------------------
// Setup: fp16 swizzled candidate B image + exact fp32 tables.
// ---------------------------------------------------------------------------
__global__ void hadar_setup(const float* __restrict__ s_sky,
                            const float* __restrict__ s_ground,
                            const float* __restrict__ library,
                            const float* __restrict__ wg) {
    __shared__ float sh_xamb[CC];
    __shared__ float sh_B[TT][CC];
    __shared__ float sh_lib[MM][CC];
    int tid = threadIdx.x;
    if (tid == 0) g_obj = 0.0;
    for (int c = tid; c < CC; c += blockDim.x)
        sh_xamb[c] = 0.5f * s_sky[c] + 0.5f * s_ground[c];
    for (int i = tid; i < MM * CC; i += blockDim.x)
        sh_lib[i / CC][i % CC] = library[i];
    for (int i = tid; i < TT * CC; i += blockDim.x) {
        int t = i / CC, c = i % CC;
        float Tk = 250.0f + (100.0f / 19.0f) * (float)t;
        float nu = wg[c];
        sh_B[t][c] = C1F * nu * nu * nu / expm1f(C2F * nu / Tk);
    }
    if (tid < TT) g_tc[tid] = 250.0f + (100.0f / 19.0f) * (float)tid;
    __syncthreads();
    if (tid < MM) {
        float s = 0.0f;
        for (int c = 0; c < CC; c++) s += sh_lib[tid][c];
        g_lm[tid] = s / (float)CC;
    }
    for (int i = tid; i < NCAND * CC; i += blockDim.x) {
        int k = i / CC, c = i % CC;
        int m = k / TT, t = k % TT;
        float e = sh_lib[m][c];
        g_candT[k * CTPAD + c] = e * sh_B[t][c] + (1.0f - e) * sh_xamb[c];
    }
    for (int k = tid; k < NCAND; k += blockDim.x) {
        int m = k / TT, t = k % TT;
        float s = 0.0f;
        for (int c = 0; c < CC; c++) {
            float e = sh_lib[m][c];
            float v = e * sh_B[t][c] + (1.0f - e) * sh_xamb[c];
            s += v * v;
        }
        g_c2[k] = s;
    }
    // fp16 B image: row n (candidate), 64 cols (54 real + 10 zeros), XOR-swizzled.
    for (int i = tid; i < NCAND * 64; i += blockDim.x) {
        int n = i / 64, c = i % 64;
        float v = 0.0f;
        if (c < CC) {
            int m = n / TT, t = n % TT;
            float e = sh_lib[m][c];
            v = e * sh_B[t][c] + (1.0f - e) * sh_xamb[c];
        }
        __half h = __float2half(v);
        uint32_t raw = (uint32_t)(2 * c);
        uint32_t phys = (uint32_t)n * BROW + (raw ^ (((uint32_t)n & 7u) << 4));
        *(__half*)(g_Bimg + phys) = h;
    }
}

// ---------------------------------------------------------------------------
// Main: persistent coarse-fp16-HMMA + sound exact-fp32 refine.
// Fully warp-decoupled tile loop: NO __syncthreads inside the loop.
// 256 threads, 8 warps; each warp owns 16 pixels of each 128-px tile.
// ---------------------------------------------------------------------------
__global__ __launch_bounds__(256, 2)
void hadar_main_mma(const float* __restrict__ s_obs,
                    const float* __restrict__ library,
                    float* __restrict__ out, int N) {
    extern __shared__ unsigned char dynsmem[];
    uint32_t raw = smem_u32(dynsmem);
    uint32_t padb = (1024u - (raw & 1023u)) & 1023u;
    uint32_t sb = raw + padb;
    unsigned char* sp = dynsmem + padb;

    int tid = threadIdx.x, wid = tid >> 5, lane = tid & 31;

    // one-time smem fill
    {
        const uint4* srcB = (const uint4*)g_Bimg;
        uint4* dstB = (uint4*)(sp + SM_B);
        for (int i = tid; i < B_IMG_BYTES / 16; i += 256) dstB[i] = srcB[i];
        const uint4* srcC = (const uint4*)g_candT;
        uint4* dstC = (uint4*)(sp + SM_CT);
        for (int i = tid; i < (NCAND * CTPAD * 4) / 16; i += 256) dstC[i] = srcC[i];
        float* c2d = (float*)(sp + SM_C2);
        for (int i = tid; i < NCAND; i += 256) c2d[i] = g_c2[i];
        if (tid < TT) ((float*)(sp + SM_TC))[tid] = g_tc[tid];
        if (tid < MM) ((float*)(sp + SM_LM))[tid] = g_lm[tid];
        float* libd = (float*)(sp + SM_LIB);
        for (int i = tid; i < MM * CC; i += 256) libd[i] = library[i];
    }
    __syncthreads();

    long long NN = N;
    int tiles = (N + TILE_M - 1) / TILE_M;
    double acc = 0.0;            // Σ minv (own pixels) + Σ x^2+y^2 (own loads)

    const int r0 = wid << 4;     // warp's first row in the 128-row tile
    const uint32_t abase = sb + SM_A + (uint32_t)r0 * AROW;
    const int a_mi = lane >> 3;
    const uint32_t a_row = (uint32_t)(((a_mi & 1) << 3) + (lane & 7));
    const uint32_t a_sw = (a_row & 7u) << 4;
    const uint32_t a_hi16 = (uint32_t)((a_mi >> 1) << 4);
    const uint32_t a_rowoff = abase + a_row * AROW;
    const uint32_t b4_row = (uint32_t)(((lane >> 4) << 3) + (lane & 7));
    const uint32_t b4_sw = ((uint32_t)(lane & 7)) << 4;
    const uint32_t b4_hi16 = (uint32_t)(((lane >> 3) & 1) << 4);
    const uint32_t b4_base = sb + SM_B + b4_row * BROW;
    const int l15 = lane & 15;
    const uint32_t b2_sw = ((uint32_t)(l15 & 7)) << 4;
    const uint32_t b2_hi16 = (uint32_t)((l15 >> 3) << 4);
    const uint32_t b2_base = sb + SM_B + (uint32_t)(14 * 8 + (l15 & 7)) * BROW;

    const float* c2s = (const float*)(sp + SM_C2);
    const int ra = r0 + (lane >> 2);              // row a; row b = ra + 8
    const int colbase = 2 * (lane & 3);
    int* mkw = (int*)(sp + SM_MINK) + r0;         // warp-private slots
    float* mvw = (float*)(sp + SM_MINV) + r0;

    // ---- prologue: prefetch first tile into registers (MLP=16) ----
    float2 pv[16];
    {
        long long base0 = (long long)blockIdx.x * TILE_M;
#pragma unroll
        for (int rr = 0; rr < 16; rr++) {
            long long n = base0 + r0 + rr;
            pv[rr] = make_float2(0.0f, 0.0f);
            if (blockIdx.x < tiles && n < N && lane < CP)
                pv[rr] = *(const float2*)(s_obs + n * CC + 2 * lane);
        }
    }

    for (int tile = blockIdx.x; tile < tiles; tile += gridDim.x) {
        long long base = (long long)tile * TILE_M;
        long long wbase = base + r0;

        // ---- stage A from registers: fp16 swizzled + fp32 copy (warp-local) ----
        float tp2 = 0.0f;
#pragma unroll
        for (int rr = 0; rr < 16; rr++) {
            int r = r0 + rr;
            float x = pv[rr].x, y = pv[rr].y;
            tp2 = fmaf(x, x, fmaf(y, y, tp2));
            __half2 h2 = __floats2half2_rn(x, y);
            uint32_t hp = *(uint32_t*)&h2;
            uint32_t sw = ((uint32_t)r & 7u) << 4;
            *(uint32_t*)(sp + SM_A + (uint32_t)r * AROW + ((4u * (uint32_t)lane) ^ sw)) = hp;
            if (lane < 28)
                ((float2*)(sp + SM_A32))[r * 28 + lane] = make_float2(x, y);
        }
        acc += (double)tp2;
        __syncwarp();

        // ---- coarse HMMA: D[16 x 120], K=64 fp16 (warp-local A rows) ----
        float d[NNT * 4];
#pragma unroll
        for (int i = 0; i < NNT * 4; i++) d[i] = 0.0f;

#pragma unroll
        for (int s = 0; s < 4; s++) {
            uint32_t koff = (uint32_t)s * 32u;
            uint32_t a0, a1, a2, a3;
            ldsm_x4(a0, a1, a2, a3, a_rowoff + ((koff + a_hi16) ^ a_sw));
            uint32_t bk4 = (koff + b4_hi16) ^ b4_sw;
#pragma unroll
            for (int q = 0; q < 7; q++) {
                uint32_t b0, b1, b2, b3;
                ldsm_x4(b0, b1, b2, b3, b4_base + (uint32_t)q * (16u * BROW) + bk4);
                mma16816h(d + (2 * q) * 4,     a0, a1, a2, a3, b0, b1);
                mma16816h(d + (2 * q + 1) * 4, a0, a1, a2, a3, b2, b3);
            }
            {
                uint32_t b0, b1;
                ldsm_x2(b0, b1, b2_base + ((koff + b2_hi16) ^ b2_sw));
                mma16816h(d + 14 * 4, a0, a1, a2, a3, b0, b1);
            }
        }

        // ---- pass 1: per-row m1 = min(val + bound) ----
        float m1a = 3.402823e38f, m1b = 3.402823e38f;
#pragma unroll
        for (int nt = 0; nt < NNT; nt++) {
            int k0 = nt * 8 + colbase;
            float c20 = c2s[k0], c21 = c2s[k0 + 1];
            float dotA0 = d[nt * 4 + 0], dotA1 = d[nt * 4 + 1];
            float dotB0 = d[nt * 4 + 2], dotB1 = d[nt * 4 + 3];
            m1a = fminf(m1a, fmaf(-2.0f, dotA0, c20) + fmaf(0.0022f, dotA0, 1e-6f));
            m1a = fminf(m1a, fmaf(-2.0f, dotA1, c21) + fmaf(0.0022f, dotA1, 1e-6f));
            m1b = fminf(m1b, fmaf(-2.0f, dotB0, c20) + fmaf(0.0022f, dotB0, 1e-6f));
            m1b = fminf(m1b, fmaf(-2.0f, dotB1, c21) + fmaf(0.0022f, dotB1, 1e-6f));
        }
#pragma unroll
        for (int off = 1; off <= 2; off <<= 1) {
            m1a = fminf(m1a, __shfl_xor_sync(0xffffffffu, m1a, off));
            m1b = fminf(m1b, __shfl_xor_sync(0xffffffffu, m1b, off));
        }

        // ---- pass 2: shortlist masks ----
        uint32_t maskA = 0, maskB = 0;
#pragma unroll
        for (int nt = 0; nt < NNT; nt++) {
            int k0 = nt * 8 + colbase;
            float c20 = c2s[k0], c21 = c2s[k0 + 1];
            float dotA0 = d[nt * 4 + 0], dotA1 = d[nt * 4 + 1];
            float dotB0 = d[nt * 4 + 2], dotB1 = d[nt * 4 + 3];
            if (fmaf(-2.0f, dotA0, c20) - fmaf(0.0022f, dotA0, 1e-6f) <= m1a) maskA |= 1u << (2 * nt);
            if (fmaf(-2.0f, dotA1, c21) - fmaf(0.0022f, dotA1, 1e-6f) <= m1a) maskA |= 1u << (2 * nt + 1);
            if (fmaf(-2.0f, dotB0, c20) - fmaf(0.0022f, dotB0, 1e-6f) <= m1b) maskB |= 1u << (2 * nt);
            if (fmaf(-2.0f, dotB1, c21) - fmaf(0.0022f, dotB1, 1e-6f) <= m1b) maskB |= 1u << (2 * nt + 1);
        }

        // ---- pass 3: exact fp32 refine ----
        float bva = 3.402823e38f, bvb = 3.402823e38f;
        int bka = NCAND, bkb = NCAND;
        {
            const float2* srowA = (const float2*)(sp + SM_A32) + ra * 28;
            uint32_t mk = maskA;
            while (mk) {
                int i = __ffs(mk) - 1; mk &= mk - 1;
                int k = ((i >> 1) << 3) + colbase + (i & 1);
                const float2* crow = (const float2*)(sp + SM_CT + (uint32_t)k * (CTPAD * 4));
                float dt = 0.0f;
#pragma unroll
                for (int j = 0; j < CP; j++) {
                    float2 sv = srowA[j], cv = crow[j];
                    dt = fmaf(sv.x, cv.x, dt);
                    dt = fmaf(sv.y, cv.y, dt);
                }
                float ev = fmaf(-2.0f, dt, c2s[k]);
                if (ev < bva || (ev == bva && k < bka)) { bva = ev; bka = k; }
            }
            const float2* srowB = srowA + 8 * 28;
            mk = maskB;
            while (mk) {
                int i = __ffs(mk) - 1; mk &= mk - 1;
                int k = ((i >> 1) << 3) + colbase + (i & 1);
                const float2* crow = (const float2*)(sp + SM_CT + (uint32_t)k * (CTPAD * 4));
                float dt = 0.0f;
#pragma unroll
                for (int j = 0; j < CP; j++) {
                    float2 sv = srowB[j], cv = crow[j];
                    dt = fmaf(sv.x, cv.x, dt);
                    dt = fmaf(sv.y, cv.y, dt);
                }
                float ev = fmaf(-2.0f, dt, c2s[k]);
                if (ev < bvb || (ev == bvb && k < bkb)) { bvb = ev; bkb = k; }
            }
        }
#pragma unroll
        for (int off = 1; off <= 2; off <<= 1) {
            float ov = __shfl_xor_sync(0xffffffffu, bva, off);
            int   ok = __shfl_xor_sync(0xffffffffu, bka, off);
            if (ov < bva || (ov == bva && ok < bka)) { bva = ov; bka = ok; }
            ov = __shfl_xor_sync(0xffffffffu, bvb, off);
            ok = __shfl_xor_sync(0xffffffffu, bkb, off);
            if (ov < bvb || (ov == bvb && ok < bkb)) { bvb = ov; bkb = ok; }
        }
        if ((lane & 3) == 0) {
            int q = lane >> 2;
            mkw[q] = bka;
            mvw[q] = bva;
            mkw[q + 8] = bkb;
            mvw[q + 8] = bvb;
        }
        __syncwarp();

        // ---- prefetch next tile (flies during epilogue stores) ----
        {
            int ntile = tile + gridDim.x;
            long long nbase = (long long)ntile * TILE_M;
#pragma unroll
            for (int rr = 0; rr < 16; rr++) {
                long long n = nbase + r0 + rr;
                pv[rr] = make_float2(0.0f, 0.0f);
                if (ntile < tiles && n < N && lane < CP)
                    pv[rr] = *(const float2*)(s_obs + n * CC + 2 * lane);
            }
        }

        // ---- scalar outputs (lanes 0..15, own pixels) ----
        if (lane < 16) {
            long long n = wbase + lane;
            if (n < N) {
                int kmin = mkw[lane];
                int m = kmin / TT;
                out[n] = ((const float*)(sp + SM_TC))[kmin - m * TT];
                out[55 * NN + n] = 0.5f;
                out[56 * NN + n] = 0.0f;
                out[57 * NN + n] = ((const float*)(sp + SM_LM))[m];
                acc += (double)mvw[lane];
            }
        }

        // ---- warp-local coalesced best_e + s_recon (own 16 pixels) ----
        {
            long long rem = N - wbase;
            int npx = rem < 16 ? (rem < 0 ? 0 : (int)rem) : 16;
            int limit = npx * CP;                       // up to 432 float2 elems
            float2* eo = (float2*)(out + NN) + wbase * CP;
            float2* ro = (float2*)(out + 58 * NN) + wbase * CP;
            const float* libs = (const float*)(sp + SM_LIB);
            for (int i = lane; i < limit; i += 32) {
                int p = i / CP;
                int j = i - p * CP;
                int k = mkw[p];
                int m = k / TT;
                float2 e = *(const float2*)(libs + m * CC + 2 * j);
                float2 rv = ((const float2*)(sp + SM_CT + (uint32_t)k * (CTPAD * 4)))[j];
                eo[i] = e;
                ro[i] = rv;
            }
        }
        __syncwarp();
    }

    // ---- objective reduce ----
    __syncthreads();
    double* red = (double*)(sp + SM_A);
    red[tid] = acc;
    __syncthreads();
#pragma unroll
    for (int s = 128; s > 0; s >>= 1) {
        if (tid < s) red[tid] += red[tid + s];
        __syncthreads();
    }
    if (tid == 0) atomicAdd(&g_obj, red[0]);
}

__global__ void hadar_finalize(float* __restrict__ out, int N) {
    out[112LL * N] = (float)(g_obj / (double)N);
}

// ---------------------------------------------------------------------------
extern "C" void kernel_launch(void* const* d_in, const int* in_sizes, int n_in,
                              void* d_out, int out_size) {
    const float* s_obs    = (const float*)d_in[0];
    const float* s_sky    = (const float*)d_in[1];
    const float* s_ground = (const float*)d_in[2];
    const float* library  = (const float*)d_in[3];
    const float* wg       = (const float*)d_in[4];
    float* out = (float*)d_out;
    int C = in_sizes[1];           // 54
    int N = in_sizes[0] / C;       // 1048576

    cudaFuncSetAttribute(hadar_main_mma, cudaFuncAttributeMaxDynamicSharedMemorySize, DYNSMEM);

    hadar_setup<<<1, 512>>>(s_sky, s_ground, library, wg);
    hadar_main_mma<<<296, 256, DYNSMEM>>>(s_obs, library, out, N);
    hadar_finalize<<<1, 1>>>(out, N);
}

// round 14
// speedup vs baseline: 2.5094x; 1.0940x over previous
#include <cuda_runtime.h>
#include <cuda_fp16.h>
#include <cstdint>

// ---------------- problem constants ----------------
#define CC   54
#define CP   27
#define MM   6
#define TT   20
#define NCAND 120
#define CTPAD 56
#define C1F  1.191042e-8f
#define C2F  1.4387752f

// ---------------- mma tile config ----------------
#define TILE_M 128                 // pixels per block tile (8 warps x 16)
#define NNT    15                  // n-tiles of 8 (120 candidates)
#define AROW   128                 // bytes per A row (64 fp16)
#define BROW   128                 // bytes per B row (64 fp16)
#define A32ROW 216                 // bytes per fp32 s_obs row (27 float2)
#define B_IMG_BYTES (NCAND * BROW) // 15360

// smem layout (byte offsets from 1024-aligned base)
#define SM_A    0                  // 128 x 128B swizzled fp16 A tile      (16384)
#define SM_B    16384              // 120 x 128B swizzled fp16 candidates  (15360)
#define SM_A32  31744              // 128 x 216B fp32 s_obs rows           (27648)
#define SM_CT   59392              // 120 x 56 f32 exact candidate rows    (26880)
#define SM_C2P  86272              // 120 f32: c2 + 1e-6   (pad 512)
#define SM_C2M  86784              // 120 f32: c2 - 1e-6   (pad 512)
#define SM_MINV 87296              // 128 f32
#define SM_MINK 87808              // 128 i32
#define SM_TC   88320              // 20 f32
#define SM_LM   88400              // 8 f32
#define SM_LIB  88432              // 6*54 f32
#define SM_END  89728
#define DYNSMEM (SM_END + 1024)

// ---------------- device globals ----------------
__device__ __align__(16) unsigned char g_Bimg[B_IMG_BYTES];
__device__ __align__(16) float g_candT[NCAND * CTPAD];
__device__ float  g_c2[NCAND];
__device__ float  g_tc[TT];
__device__ float  g_lm[MM];
__device__ double g_obj;

__device__ __forceinline__ uint32_t smem_u32(const void* p) {
    uint32_t a;
    asm("{ .reg .u64 t; cvta.to.shared.u64 t, %1; cvt.u32.u64 %0, t; }" : "=r"(a) : "l"(p));
    return a;
}
__device__ __forceinline__ void ldsm_x4(uint32_t& r0, uint32_t& r1, uint32_t& r2, uint32_t& r3, uint32_t addr) {
    asm volatile("ldmatrix.sync.aligned.m8n8.x4.shared.b16 {%0,%1,%2,%3}, [%4];"
        : "=r"(r0), "=r"(r1), "=r"(r2), "=r"(r3) : "r"(addr));
}
__device__ __forceinline__ void ldsm_x2(uint32_t& r0, uint32_t& r1, uint32_t addr) {
    asm volatile("ldmatrix.sync.aligned.m8n8.x2.shared.b16 {%0,%1}, [%2];"
        : "=r"(r0), "=r"(r1) : "r"(addr));
}
__device__ __forceinline__ void mma16816h(float* d, uint32_t a0, uint32_t a1, uint32_t a2, uint32_t a3,
                                          uint32_t b0, uint32_t b1) {
    asm volatile("mma.sync.aligned.m16n8k16.row.col.f32.f16.f16.f32 "
        "{%0,%1,%2,%3}, {%4,%5,%6,%7}, {%8,%9}, {%0,%1,%2,%3};"
        : "+f"(d[0]), "+f"(d[1]), "+f"(d[2]), "+f"(d[3])
        : "r"(a0), "r"(a1), "r"(a2), "r"(a3), "r"(b0), "r"(b1));
}
__device__ __forceinline__ void cp_async8(uint32_t dst, const void* src) {
    asm volatile("cp.async.ca.shared.global [%0], [%1], 8;" :: "r"(dst), "l"(src) : "memory");
}
__device__ __forceinline__ void cp_async_commit() {
    asm volatile("cp.async.commit_group;" ::: "memory");
}
__device__ __forceinline__ void cp_async_wait0() {
    asm volatile("cp.async.wait_group 0;" ::: "memory");
}

// ---------------------------------------------------------------------------
// Setup: fp16 swizzled candidate B image + exact fp32 tables.
// ---------------------------------------------------------------------------
__global__ void hadar_setup(const float* __restrict__ s_sky,
                            const float* __restrict__ s_ground,
                            const float* __restrict__ library,
                            const float* __restrict__ wg) {
    __shared__ float sh_xamb[CC];
    __shared__ float sh_B[TT][CC];
    __shared__ float sh_lib[MM][CC];
    int tid = threadIdx.x;
    if (tid == 0) g_obj = 0.0;
    for (int c = tid; c < CC; c += blockDim.x)
        sh_xamb[c] = 0.5f * s_sky[c] + 0.5f * s_ground[c];
    for (int i = tid; i < MM * CC; i += blockDim.x)
        sh_lib[i / CC][i % CC] = library[i];
    for (int i = tid; i < TT * CC; i += blockDim.x) {
        int t = i / CC, c = i % CC;
        float Tk = 250.0f + (100.0f / 19.0f) * (float)t;
        float nu = wg[c];
        sh_B[t][c] = C1F * nu * nu * nu / expm1f(C2F * nu / Tk);
    }
    if (tid < TT) g_tc[tid] = 250.0f + (100.0f / 19.0f) * (float)tid;
    __syncthreads();
    if (tid < MM) {
        float s = 0.0f;
        for (int c = 0; c < CC; c++) s += sh_lib[tid][c];
        g_lm[tid] = s / (float)CC;
    }
    for (int i = tid; i < NCAND * CC; i += blockDim.x) {
        int k = i / CC, c = i % CC;
        int m = k / TT, t = k % TT;
        float e = sh_lib[m][c];
        g_candT[k * CTPAD + c] = e * sh_B[t][c] + (1.0f - e) * sh_xamb[c];
    }
    for (int k = tid; k < NCAND; k += blockDim.x) {
        int m = k / TT, t = k % TT;
        float s = 0.0f;
        for (int c = 0; c < CC; c++) {
            float e = sh_lib[m][c];
            float v = e * sh_B[t][c] + (1.0f - e) * sh_xamb[c];
            s += v * v;
        }
        g_c2[k] = s;
    }
    // fp16 B image: row n (candidate), 64 cols (54 real + 10 zeros), XOR-swizzled.
    for (int i = tid; i < NCAND * 64; i += blockDim.x) {
        int n = i / 64, c = i % 64;
        float v = 0.0f;
        if (c < CC) {
            int m = n / TT, t = n % TT;
            float e = sh_lib[m][c];
            v = e * sh_B[t][c] + (1.0f - e) * sh_xamb[c];
        }
        __half h = __float2half(v);
        uint32_t raw = (uint32_t)(2 * c);
        uint32_t phys = (uint32_t)n * BROW + (raw ^ (((uint32_t)n & 7u) << 4));
        *(__half*)(g_Bimg + phys) = h;
    }
}

// ---------------------------------------------------------------------------
// Main: persistent coarse-fp16-HMMA + sound exact-fp32 refine.
// Warp-decoupled tile loop; cp.async smem prefetch (no register prefetch).
// 256 threads, 8 warps; each warp owns 16 pixels of each 128-px tile.
// ---------------------------------------------------------------------------
__global__ __launch_bounds__(256, 2)
void hadar_main_mma(const float* __restrict__ s_obs,
                    const float* __restrict__ library,
                    float* __restrict__ out, int N) {
    extern __shared__ unsigned char dynsmem[];
    uint32_t raw = smem_u32(dynsmem);
    uint32_t padb = (1024u - (raw & 1023u)) & 1023u;
    uint32_t sb = raw + padb;
    unsigned char* sp = dynsmem + padb;

    int tid = threadIdx.x, wid = tid >> 5, lane = tid & 31;

    // one-time smem fill
    {
        const uint4* srcB = (const uint4*)g_Bimg;
        uint4* dstB = (uint4*)(sp + SM_B);
        for (int i = tid; i < B_IMG_BYTES / 16; i += 256) dstB[i] = srcB[i];
        const uint4* srcC = (const uint4*)g_candT;
        uint4* dstC = (uint4*)(sp + SM_CT);
        for (int i = tid; i < (NCAND * CTPAD * 4) / 16; i += 256) dstC[i] = srcC[i];
        float* c2p = (float*)(sp + SM_C2P);
        float* c2m = (float*)(sp + SM_C2M);
        for (int i = tid; i < NCAND; i += 256) {
            float v = g_c2[i];
            c2p[i] = v + 1e-6f;
            c2m[i] = v - 1e-6f;
        }
        if (tid < TT) ((float*)(sp + SM_TC))[tid] = g_tc[tid];
        if (tid < MM) ((float*)(sp + SM_LM))[tid] = g_lm[tid];
        float* libd = (float*)(sp + SM_LIB);
        for (int i = tid; i < MM * CC; i += 256) libd[i] = library[i];
    }
    __syncthreads();

    long long NN = N;
    int tiles = (N + TILE_M - 1) / TILE_M;
    double acc = 0.0;            // Σ minv (own pixels) + Σ x^2+y^2 (own elements)

    const int r0 = wid << 4;     // warp's first row in the 128-row tile
    const uint32_t abase = sb + SM_A + (uint32_t)r0 * AROW;
    const int a_mi = lane >> 3;
    const uint32_t a_row = (uint32_t)(((a_mi & 1) << 3) + (lane & 7));
    const uint32_t a_sw = (a_row & 7u) << 4;
    const uint32_t a_hi16 = (uint32_t)((a_mi >> 1) << 4);
    const uint32_t a_rowoff = abase + a_row * AROW;
    const uint32_t b4_row = (uint32_t)(((lane >> 4) << 3) + (lane & 7));
    const uint32_t b4_sw = ((uint32_t)(lane & 7)) << 4;
    const uint32_t b4_hi16 = (uint32_t)(((lane >> 3) & 1) << 4);
    const uint32_t b4_base = sb + SM_B + b4_row * BROW;
    const int l15 = lane & 15;
    const uint32_t b2_sw = ((uint32_t)(l15 & 7)) << 4;
    const uint32_t b2_hi16 = (uint32_t)((l15 >> 3) << 4);
    const uint32_t b2_base = sb + SM_B + (uint32_t)(14 * 8 + (l15 & 7)) * BROW;

    const float* c2ps = (const float*)(sp + SM_C2P);
    const float* c2ms = (const float*)(sp + SM_C2M);
    const int ra = r0 + (lane >> 2);              // row a; row b = ra + 8
    const int colbase = 2 * (lane & 3);
    int* mkw = (int*)(sp + SM_MINK) + r0;         // warp-private slots
    float* mvw = (float*)(sp + SM_MINV) + r0;
    const uint32_t a32w = sb + SM_A32 + (uint32_t)r0 * A32ROW + (uint32_t)lane * 8u;

    // ---- prologue: cp.async first tile into own A32 rows ----
    {
        long long base0 = (long long)blockIdx.x * TILE_M + r0;
        if (blockIdx.x < tiles && lane < CP) {
#pragma unroll
            for (int rr = 0; rr < 16; rr++) {
                long long n = base0 + rr;
                if (n < N)
                    cp_async8(a32w + (uint32_t)rr * A32ROW, s_obs + n * CC + 2 * lane);
            }
        }
        cp_async_commit();
    }

    for (int tile = blockIdx.x; tile < tiles; tile += gridDim.x) {
        long long base = (long long)tile * TILE_M;
        long long wbase = base + r0;

        cp_async_wait0();
        __syncwarp();

        // ---- stage A: read fp32 rows from smem, convert, fp16 swizzled STS ----
        float tp2 = 0.0f;
#pragma unroll
        for (int rr = 0; rr < 16; rr++) {
            int r = r0 + rr;
            float x = 0.0f, y = 0.0f;
            if (lane < CP) {
                float2 v = *(const float2*)(sp + SM_A32 + (uint32_t)r * A32ROW + (uint32_t)lane * 8u);
                x = v.x; y = v.y;
            }
            tp2 = fmaf(x, x, fmaf(y, y, tp2));
            __half2 h2 = __floats2half2_rn(x, y);
            uint32_t hp = *(uint32_t*)&h2;
            uint32_t sw = ((uint32_t)r & 7u) << 4;
            *(uint32_t*)(sp + SM_A + (uint32_t)r * AROW + ((4u * (uint32_t)lane) ^ sw)) = hp;
        }
        acc += (double)tp2;
        __syncwarp();

        // ---- coarse HMMA: D[16 x 120], K=64 fp16 (warp-local A rows) ----
        float d[NNT * 4];
#pragma unroll
        for (int i = 0; i < NNT * 4; i++) d[i] = 0.0f;

#pragma unroll
        for (int s = 0; s < 4; s++) {
            uint32_t koff = (uint32_t)s * 32u;
            uint32_t a0, a1, a2, a3;
            ldsm_x4(a0, a1, a2, a3, a_rowoff + ((koff + a_hi16) ^ a_sw));
            uint32_t bk4 = (koff + b4_hi16) ^ b4_sw;
#pragma unroll
            for (int q = 0; q < 7; q++) {
                uint32_t b0, b1, b2, b3;
                ldsm_x4(b0, b1, b2, b3, b4_base + (uint32_t)q * (16u * BROW) + bk4);
                mma16816h(d + (2 * q) * 4,     a0, a1, a2, a3, b0, b1);
                mma16816h(d + (2 * q + 1) * 4, a0, a1, a2, a3, b2, b3);
            }
            {
                uint32_t b0, b1;
                ldsm_x2(b0, b1, b2_base + ((koff + b2_hi16) ^ b2_sw));
                mma16816h(d + 14 * 4, a0, a1, a2, a3, b0, b1);
            }
        }

        // ---- pass 1: m1 = min(hi) where hi = c2+1e-6 - 1.9978*dot ----
        float m1a = 3.402823e38f, m1b = 3.402823e38f;
#pragma unroll
        for (int nt = 0; nt < NNT; nt++) {
            int k0 = nt * 8 + colbase;
            float p0 = c2ps[k0], p1 = c2ps[k0 + 1];
            m1a = fminf(m1a, fmaf(-1.9978f, d[nt * 4 + 0], p0));
            m1a = fminf(m1a, fmaf(-1.9978f, d[nt * 4 + 1], p1));
            m1b = fminf(m1b, fmaf(-1.9978f, d[nt * 4 + 2], p0));
            m1b = fminf(m1b, fmaf(-1.9978f, d[nt * 4 + 3], p1));
        }
#pragma unroll
        for (int off = 1; off <= 2; off <<= 1) {
            m1a = fminf(m1a, __shfl_xor_sync(0xffffffffu, m1a, off));
            m1b = fminf(m1b, __shfl_xor_sync(0xffffffffu, m1b, off));
        }

        // ---- pass 2: shortlist masks (lo = c2-1e-6 - 2.0022*dot <= m1) ----
        uint32_t maskA = 0, maskB = 0;
#pragma unroll
        for (int nt = 0; nt < NNT; nt++) {
            int k0 = nt * 8 + colbase;
            float q0 = c2ms[k0], q1 = c2ms[k0 + 1];
            if (fmaf(-2.0022f, d[nt * 4 + 0], q0) <= m1a) maskA |= 1u << (2 * nt);
            if (fmaf(-2.0022f, d[nt * 4 + 1], q1) <= m1a) maskA |= 1u << (2 * nt + 1);
            if (fmaf(-2.0022f, d[nt * 4 + 2], q0) <= m1b) maskB |= 1u << (2 * nt);
            if (fmaf(-2.0022f, d[nt * 4 + 3], q1) <= m1b) maskB |= 1u << (2 * nt + 1);
        }

        // ---- pass 3: exact fp32 refine ----
        float bva = 3.402823e38f, bvb = 3.402823e38f;
        int bka = NCAND, bkb = NCAND;
        {
            const float2* srowA = (const float2*)(sp + SM_A32 + (uint32_t)ra * A32ROW);
            uint32_t mk = maskA;
            while (mk) {
                int i = __ffs(mk) - 1; mk &= mk - 1;
                int k = ((i >> 1) << 3) + colbase + (i & 1);
                const float2* crow = (const float2*)(sp + SM_CT + (uint32_t)k * (CTPAD * 4));
                float dt = 0.0f;
#pragma unroll
                for (int j = 0; j < CP; j++) {
                    float2 sv = srowA[j], cv = crow[j];
                    dt = fmaf(sv.x, cv.x, dt);
                    dt = fmaf(sv.y, cv.y, dt);
                }
                float ev = fmaf(-2.0f, dt, c2ps[k] - 1e-6f);
                if (ev < bva || (ev == bva && k < bka)) { bva = ev; bka = k; }
            }
            const float2* srowB = (const float2*)(sp + SM_A32 + (uint32_t)(ra + 8) * A32ROW);
            mk = maskB;
            while (mk) {
                int i = __ffs(mk) - 1; mk &= mk - 1;
                int k = ((i >> 1) << 3) + colbase + (i & 1);
                const float2* crow = (const float2*)(sp + SM_CT + (uint32_t)k * (CTPAD * 4));
                float dt = 0.0f;
#pragma unroll
                for (int j = 0; j < CP; j++) {
                    float2 sv = srowB[j], cv = crow[j];
                    dt = fmaf(sv.x, cv.x, dt);
                    dt = fmaf(sv.y, cv.y, dt);
                }
                float ev = fmaf(-2.0f, dt, c2ps[k] - 1e-6f);
                if (ev < bvb || (ev == bvb && k < bkb)) { bvb = ev; bkb = k; }
            }
        }
#pragma unroll
        for (int off = 1; off <= 2; off <<= 1) {
            float ov = __shfl_xor_sync(0xffffffffu, bva, off);
            int   ok = __shfl_xor_sync(0xffffffffu, bka, off);
            if (ov < bva || (ov == bva && ok < bka)) { bva = ov; bka = ok; }
            ov = __shfl_xor_sync(0xffffffffu, bvb, off);
            ok = __shfl_xor_sync(0xffffffffu, bkb, off);
            if (ov < bvb || (ov == bvb && ok < bkb)) { bvb = ov; bkb = ok; }
        }
        if ((lane & 3) == 0) {
            int q = lane >> 2;
            mkw[q] = bka;
            mvw[q] = bva;
            mkw[q + 8] = bkb;
            mvw[q + 8] = bvb;
        }
        __syncwarp();    // all refine reads of A32 done; mink visible

        // ---- cp.async next tile into own A32 rows (flies during epilogue) ----
        {
            int ntile = tile + gridDim.x;
            if (ntile < tiles && lane < CP) {
                long long nbase = (long long)ntile * TILE_M + r0;
#pragma unroll
                for (int rr = 0; rr < 16; rr++) {
                    long long n = nbase + rr;
                    if (n < N)
                        cp_async8(a32w + (uint32_t)rr * A32ROW, s_obs + n * CC + 2 * lane);
                }
            }
            cp_async_commit();
        }

        // ---- scalar outputs (lanes 0..15, own pixels) ----
        if (lane < 16) {
            long long n = wbase + lane;
            if (n < N) {
                int kmin = mkw[lane];
                int m = kmin / TT;
                out[n] = ((const float*)(sp + SM_TC))[kmin - m * TT];
                out[55 * NN + n] = 0.5f;
                out[56 * NN + n] = 0.0f;
                out[57 * NN + n] = ((const float*)(sp + SM_LM))[m];
                acc += (double)mvw[lane];
            }
        }

        // ---- warp-local coalesced best_e + s_recon (own 16 pixels) ----
        {
            long long rem = N - wbase;
            int npx = rem < 16 ? (rem < 0 ? 0 : (int)rem) : 16;
            int limit = npx * CP;                       // up to 432 float2 elems
            float2* eo = (float2*)(out + NN) + wbase * CP;
            float2* ro = (float2*)(out + 58 * NN) + wbase * CP;
            const float* libs = (const float*)(sp + SM_LIB);
            for (int i = lane; i < limit; i += 32) {
                int p = i / CP;
                int j = i - p * CP;
                int k = mkw[p];
                int m = k / TT;
                float2 e = *(const float2*)(libs + m * CC + 2 * j);
                float2 rv = ((const float2*)(sp + SM_CT + (uint32_t)k * (CTPAD * 4)))[j];
                eo[i] = e;
                ro[i] = rv;
            }
        }
        __syncwarp();
    }

    // ---- objective reduce ----
    __syncthreads();
    double* red = (double*)(sp + SM_A);
    red[tid] = acc;
    __syncthreads();
#pragma unroll
    for (int s = 128; s > 0; s >>= 1) {
        if (tid < s) red[tid] += red[tid + s];
        __syncthreads();
    }
    if (tid == 0) atomicAdd(&g_obj, red[0]);
}

__global__ void hadar_finalize(float* __restrict__ out, int N) {
    out[112LL * N] = (float)(g_obj / (double)N);
}

// ---------------------------------------------------------------------------
extern "C" void kernel_launch(void* const* d_in, const int* in_sizes, int n_in,
                              void* d_out, int out_size) {
    const float* s_obs    = (const float*)d_in[0];
    const float* s_sky    = (const float*)d_in[1];
    const float* s_ground = (const float*)d_in[2];
    const float* library  = (const float*)d_in[3];
    const float* wg       = (const float*)d_in[4];
    float* out = (float*)d_out;
    int C = in_sizes[1];           // 54
    int N = in_sizes[0] / C;       // 1048576

    cudaFuncSetAttribute(hadar_main_mma, cudaFuncAttributeMaxDynamicSharedMemorySize, DYNSMEM);

    hadar_setup<<<1, 512>>>(s_sky, s_ground, library, wg);
    hadar_main_mma<<<296, 256, DYNSMEM>>>(s_obs, library, out, N);
    hadar_finalize<<<1, 1>>>(out, N);
}